// round 6
// baseline (speedup 1.0000x reference)
#include <cuda_runtime.h>
#include <cuda_fp16.h>
#include <cstdint>

#define B_DIM 8
#define R_DIM 128
#define H_DIM 4096
#define W_DIM 4096
#define KSPLIT 16

// Scratch (device globals: allocation-free per harness rules)
__device__ float  g_part[KSPLIT * B_DIM * R_DIM * R_DIM]; // 8 MB partial Gram
__device__ float  g_Ci[B_DIM * R_DIM * R_DIM];            // 512KB C^-1
__device__ __half g_Pth[B_DIM * R_DIM * W_DIM];           // 8 MB Pt hi (fp16)
__device__ __half g_Ptl[B_DIM * R_DIM * W_DIM];           // 8 MB Pt lo (fp16)

// ---------------------------------------------------------------------------
// K1: partial Gram  part[ks][b][r][s] = sum_{w in split} N[r][w]*N[s][w]
// One block computes the full 128x128 tile for its (ks, b); 8x8 reg tiles.
// Smem stored K-major (transposed) so operand loads are LDS.128.
// ---------------------------------------------------------------------------
__global__ void __launch_bounds__(256) k1_gram(const float* __restrict__ N) {
    __shared__ float Ns[32][132];
    int ks = blockIdx.x, b = blockIdx.y;
    int tid = threadIdx.x;
    int tx = tid & 15, ty = tid >> 4;
    const float* Nb = N + (size_t)b * R_DIM * W_DIM;

    float acc[8][8];
#pragma unroll
    for (int i = 0; i < 8; i++)
#pragma unroll
        for (int j = 0; j < 8; j++) acc[i][j] = 0.f;

    int k0 = ks * (W_DIM / KSPLIT);            // 256 columns per split
    for (int kk = k0; kk < k0 + W_DIM / KSPLIT; kk += 32) {
#pragma unroll
        for (int i = 0; i < 4; i++) {
            int u = tid + i * 256;             // 1024 float4 units
            int row = u >> 3, j = u & 7;
            float4 v = *(const float4*)(Nb + (size_t)row * W_DIM + kk + j * 4);
            Ns[j * 4 + 0][row] = v.x;
            Ns[j * 4 + 1][row] = v.y;
            Ns[j * 4 + 2][row] = v.z;
            Ns[j * 4 + 3][row] = v.w;
        }
        __syncthreads();
#pragma unroll
        for (int k = 0; k < 32; k++) {
            float4 a0 = *(const float4*)&Ns[k][ty * 8];
            float4 a1 = *(const float4*)&Ns[k][ty * 8 + 4];
            float4 b0 = *(const float4*)&Ns[k][tx * 8];
            float4 b1 = *(const float4*)&Ns[k][tx * 8 + 4];
            float av[8] = {a0.x, a0.y, a0.z, a0.w, a1.x, a1.y, a1.z, a1.w};
            float bv[8] = {b0.x, b0.y, b0.z, b0.w, b1.x, b1.y, b1.z, b1.w};
#pragma unroll
            for (int i = 0; i < 8; i++)
#pragma unroll
                for (int j = 0; j < 8; j++)
                    acc[i][j] = fmaf(av[i], bv[j], acc[i][j]);
        }
        __syncthreads();
    }
    float* P = g_part + (size_t)(ks * B_DIM + b) * 16384;
#pragma unroll
    for (int i = 0; i < 8; i++)
#pragma unroll
        for (int j = 0; j < 8; j += 4)
            *(float4*)&P[(ty * 8 + i) * 128 + tx * 8 + j] =
                make_float4(acc[i][j], acc[i][j + 1], acc[i][j + 2], acc[i][j + 3]);
}

// ---------------------------------------------------------------------------
// K2: C = alpha*I + 2*gamma*G; register-resident Gauss-Jordan inverse.
// ---------------------------------------------------------------------------
__global__ void __launch_bounds__(1024, 1) k2_inv(const float* __restrict__ alpha,
                                                  const float* __restrict__ gamma) {
    __shared__ float s_rowk[2][128];
    __shared__ float s_colk[2][128];
    __shared__ float s_invp[2];

    int b = blockIdx.x;
    int t = threadIdx.x;
    int i  = t >> 3;
    int jc = (t & 7) << 4;
    float a  = alpha[b];
    float g2 = 2.0f * gamma[b];

    float M[16];
#pragma unroll
    for (int q = 0; q < 16; q++) {
        int e = i * 128 + jc + q;
        float s = 0.f;
#pragma unroll
        for (int p = 0; p < KSPLIT; p++)
            s += g_part[((size_t)(p * B_DIM + b)) * 16384 + e];
        M[q] = g2 * s + ((jc + q) == i ? a : 0.f);
    }
    if (i == 0) {
#pragma unroll
        for (int q = 0; q < 16; q++) s_rowk[0][jc + q] = M[q];
        if (jc == 0) s_invp[0] = 1.0f / M[0];
    }
    if (jc == 0) s_colk[0][i] = M[0];
    __syncthreads();

    for (int k = 0; k < 128; k++) {
        int par = k & 1;
        float ip = s_invp[par];
        if (i == k) {
#pragma unroll
            for (int q = 0; q < 16; q++) M[q] *= ip;
            if (k >= jc && k < jc + 16) M[k - jc] = ip;
        } else {
            float c = s_colk[par][i] * ip;
#pragma unroll
            for (int q = 0; q < 16; q++)
                M[q] = fmaf(-c, s_rowk[par][jc + q], M[q]);
            if (k >= jc && k < jc + 16) M[k - jc] = -c;
        }
        int kn = k + 1;
        if (kn < 128) {
            int pn = kn & 1;
            if (i == kn) {
#pragma unroll
                for (int q = 0; q < 16; q++) s_rowk[pn][jc + q] = M[q];
                if (kn >= jc && kn < jc + 16) s_invp[pn] = 1.0f / M[kn - jc];
            }
            if (kn >= jc && kn < jc + 16) s_colk[pn][i] = M[kn - jc];
        }
        __syncthreads();
    }

    float* Ci = g_Ci + (size_t)b * 16384;
#pragma unroll
    for (int q = 0; q < 16; q++)
        Ci[i * 128 + jc + q] = M[q];
}

// ---------------------------------------------------------------------------
// K3: Pt[b][s][w] = 2*gamma * sum_r Cinv[r][s] * N[r][w], split fp16 hi/lo.
// 4 w-columns per thread (float4 LDG), 16 s per block row-group.
// ---------------------------------------------------------------------------
__global__ void __launch_bounds__(256) k3_pt(const float* __restrict__ N,
                                             const float* __restrict__ gamma) {
    __shared__ float cs[128][17];
    int b  = blockIdx.z;
    int s0 = blockIdx.y * 16;
    int w0 = blockIdx.x * 1024 + threadIdx.x * 4;
    const float* Ci = g_Ci + (size_t)b * 16384;
    for (int e = threadIdx.x; e < 128 * 16; e += 256) {
        int r = e >> 4, sp = e & 15;
        cs[r][sp] = Ci[r * 128 + s0 + sp];
    }
    __syncthreads();

    const float* Nb = N + (size_t)b * R_DIM * W_DIM;
    float acc[16][4];
#pragma unroll
    for (int s = 0; s < 16; s++)
#pragma unroll
        for (int q = 0; q < 4; q++) acc[s][q] = 0.f;

    for (int r = 0; r < 128; r++) {
        float4 nv = *(const float4*)(Nb + (size_t)r * W_DIM + w0);
#pragma unroll
        for (int s = 0; s < 16; s++) {
            float c = cs[r][s];
            acc[s][0] = fmaf(c, nv.x, acc[s][0]);
            acc[s][1] = fmaf(c, nv.y, acc[s][1]);
            acc[s][2] = fmaf(c, nv.z, acc[s][2]);
            acc[s][3] = fmaf(c, nv.w, acc[s][3]);
        }
    }
    float g2 = 2.0f * gamma[b];
    __half* Ph = g_Pth + (size_t)b * R_DIM * W_DIM;
    __half* Pl = g_Ptl + (size_t)b * R_DIM * W_DIM;
#pragma unroll
    for (int s = 0; s < 16; s++) {
        float v0 = g2 * acc[s][0], v1 = g2 * acc[s][1];
        float v2 = g2 * acc[s][2], v3 = g2 * acc[s][3];
        __half h0 = __float2half_rn(v0), h1 = __float2half_rn(v1);
        __half h2 = __float2half_rn(v2), h3 = __float2half_rn(v3);
        __half l0 = __float2half_rn(v0 - __half2float(h0));
        __half l1 = __float2half_rn(v1 - __half2float(h1));
        __half l2 = __float2half_rn(v2 - __half2float(h2));
        __half l3 = __float2half_rn(v3 - __half2float(h3));
        __half2 hh0 = __halves2half2(h0, h1), hh1 = __halves2half2(h2, h3);
        __half2 ll0 = __halves2half2(l0, l1), ll1 = __halves2half2(l2, l3);
        size_t off = (size_t)(s0 + s) * W_DIM + w0;
        *(uint2*)(Ph + off) = make_uint2(*(uint32_t*)&hh0, *(uint32_t*)&hh1);
        *(uint2*)(Pl + off) = make_uint2(*(uint32_t*)&ll0, *(uint32_t*)&ll1);
    }
}

// ---------------------------------------------------------------------------
// K4: out[b][h][s] = sum_w A[b][h][w] * Pt[b][s][w]
// fp16 2-way split, 3x m16n8k16 HMMA fp32 accum.
// A: LDG->split->STS register pipeline. B: cp.async (already fp16 in global).
// Double buffer, ONE barrier per iteration.
// ---------------------------------------------------------------------------
#define BM 256
#define BN 128
#define BK 32
#define NTHREADS 512
#define RS 40                        // halves per smem row (80B, conflict-free)
#define AH_OFF 0
#define AL_OFF (256 * RS)            // 10240
#define BH_OFF (512 * RS)            // 20480
#define BL_OFF (640 * RS)            // 25600
#define BUF_H  (768 * RS)            // 30720 halves per stage

__device__ __forceinline__ uint32_t smem_u32(const void* p) {
    return (uint32_t)__cvta_generic_to_shared(p);
}
__device__ __forceinline__ void cp_async16(uint32_t saddr, const void* g) {
    asm volatile("cp.async.cg.shared.global [%0], [%1], 16;" :: "r"(saddr), "l"(g) : "memory");
}
__device__ __forceinline__ void ldsm_x4(uint32_t addr, uint32_t& r0, uint32_t& r1,
                                        uint32_t& r2, uint32_t& r3) {
    asm volatile("ldmatrix.sync.aligned.m8n8.x4.shared.b16 {%0,%1,%2,%3}, [%4];"
                 : "=r"(r0), "=r"(r1), "=r"(r2), "=r"(r3) : "r"(addr));
}
__device__ __forceinline__ void mma_f16(float* d, const uint32_t* a, const uint32_t* b) {
    asm volatile(
        "mma.sync.aligned.m16n8k16.row.col.f32.f16.f16.f32 "
        "{%0,%1,%2,%3}, {%4,%5,%6,%7}, {%8,%9}, {%0,%1,%2,%3};"
        : "+f"(d[0]), "+f"(d[1]), "+f"(d[2]), "+f"(d[3])
        : "r"(a[0]), "r"(a[1]), "r"(a[2]), "r"(a[3]),
          "r"(b[0]), "r"(b[1]));
}
__device__ __forceinline__ void split_h(float f, __half& h, __half& l) {
    h = __float2half_rn(f);
    l = __float2half_rn(f - __half2float(h));
}

__global__ void __launch_bounds__(NTHREADS, 1) k4_gemm(const float* __restrict__ A,
                                                       float* __restrict__ O) {
    extern __shared__ __half smh[];
    int b  = blockIdx.y;
    int m0 = blockIdx.x * BM;
    int tid = threadIdx.x;
    int lane = tid & 31, wid = tid >> 5;
    int wm = wid & 3;        // 4 warps in M -> 64 rows each
    int wn = wid >> 2;       // 4 warps in N -> 32 cols each

    const float*  Ab  = A + (size_t)b * H_DIM * W_DIM;
    const __half* Bhg = g_Pth + (size_t)b * R_DIM * W_DIM;
    const __half* Blg = g_Ptl + (size_t)b * R_DIM * W_DIM;

    float acc[4][4][4];
#pragma unroll
    for (int mt = 0; mt < 4; mt++)
#pragma unroll
        for (int nt = 0; nt < 4; nt++)
#pragma unroll
            for (int r = 0; r < 4; r++) acc[mt][nt][r] = 0.f;

    // A register staging
    float4 a4[4];
    int brow = tid >> 2, bcol = tid & 3;   // B: 128 rows x 4 units of 8 halves

    auto ldg_A = [&](int kk) {
#pragma unroll
        for (int i = 0; i < 4; i++) {
            int v = tid + i * NTHREADS;
            int row = v >> 3, kc = v & 7;
            a4[i] = *(const float4*)(Ab + (size_t)(m0 + row) * W_DIM + kk + kc * 4);
        }
    };
    auto cpb = [&](int bufsel, int kk) {
        __half* base = smh + bufsel * BUF_H;
        cp_async16(smem_u32(base + BH_OFF + brow * RS + bcol * 8),
                   Bhg + (size_t)brow * W_DIM + kk + bcol * 8);
        cp_async16(smem_u32(base + BL_OFF + brow * RS + bcol * 8),
                   Blg + (size_t)brow * W_DIM + kk + bcol * 8);
        asm volatile("cp.async.commit_group;" ::: "memory");
    };
    auto sts_A = [&](int bufsel) {
        __half* base = smh + bufsel * BUF_H;
#pragma unroll
        for (int i = 0; i < 4; i++) {
            int v = tid + i * NTHREADS;
            int row = v >> 3, kc = v & 7;
            __half hx, lx, hy, ly, hz, lz, hw, lw;
            split_h(a4[i].x, hx, lx);
            split_h(a4[i].y, hy, ly);
            split_h(a4[i].z, hz, lz);
            split_h(a4[i].w, hw, lw);
            __half2* ph = (__half2*)(base + AH_OFF + row * RS + kc * 4);
            ph[0] = __halves2half2(hx, hy);
            ph[1] = __halves2half2(hz, hw);
            __half2* pl = (__half2*)(base + AL_OFF + row * RS + kc * 4);
            pl[0] = __halves2half2(lx, ly);
            pl[1] = __halves2half2(lz, lw);
        }
    };

    ldg_A(0);
    cpb(0, 0);

    const int KITERS = W_DIM / BK; // 128
    for (int kb = 0; kb < KITERS; kb++) {
        sts_A(kb & 1);
        asm volatile("cp.async.wait_group 0;" ::: "memory");
        __syncthreads();
        if (kb + 1 < KITERS) {
            ldg_A((kb + 1) * BK);
            cpb((kb + 1) & 1, (kb + 1) * BK);
        }

        uint32_t sbase = smem_u32(smh + (kb & 1) * BUF_H);

#pragma unroll
        for (int ks = 0; ks < 2; ks++) {
            // --- B fragments (hi & lo), 4 nt-tiles ---
            uint32_t bhi[4][2], blo[4][2];
            int idx = lane >> 3;
            int kboff = ks * 32 + (idx & 1) * 16;   // bytes within 64B k-chunk
#pragma unroll
            for (int h = 0; h < 2; h++) {
                int nrow = wn * 32 + h * 16 + (idx >> 1) * 8 + (lane & 7);
                uint32_t r0, r1, r2, r3;
                ldsm_x4(sbase + (BH_OFF + nrow * RS) * 2 + kboff, r0, r1, r2, r3);
                bhi[2 * h][0] = r0; bhi[2 * h][1] = r1;
                bhi[2 * h + 1][0] = r2; bhi[2 * h + 1][1] = r3;
                ldsm_x4(sbase + (BL_OFF + nrow * RS) * 2 + kboff, r0, r1, r2, r3);
                blo[2 * h][0] = r0; blo[2 * h][1] = r1;
                blo[2 * h + 1][0] = r2; blo[2 * h + 1][1] = r3;
            }
            // --- A fragments per mt (hi & lo), 3 MMAs per (mt,nt) ---
            int karow = ks * 32 + (lane >> 4) * 16; // bytes
#pragma unroll
            for (int mt = 0; mt < 4; mt++) {
                int arow = wm * 64 + mt * 16 + (lane & 15);
                uint32_t ah[4], al[4];
                ldsm_x4(sbase + (AH_OFF + arow * RS) * 2 + karow,
                        ah[0], ah[1], ah[2], ah[3]);
                ldsm_x4(sbase + (AL_OFF + arow * RS) * 2 + karow,
                        al[0], al[1], al[2], al[3]);
#pragma unroll
                for (int nt = 0; nt < 4; nt++) {
                    mma_f16(acc[mt][nt], al, bhi[nt]);   // lo*hi
                    mma_f16(acc[mt][nt], ah, blo[nt]);   // hi*lo
                    mma_f16(acc[mt][nt], ah, bhi[nt]);   // hi*hi
                }
            }
        }
        // NOTE: no trailing barrier. sts(kb+1) at next iter top targets
        // buf[(kb+1)&1], last read by compute(kb-1) which all warps finished
        // before passing this iteration's barrier.
    }

    // Epilogue: direct float2 stores
#pragma unroll
    for (int mt = 0; mt < 4; mt++) {
#pragma unroll
        for (int nt = 0; nt < 4; nt++) {
            int r = m0 + wm * 64 + mt * 16 + (lane >> 2);
            int c = wn * 32 + nt * 8 + (lane & 3) * 2;
            float2 v0 = make_float2(acc[mt][nt][0], acc[mt][nt][1]);
            float2 v1 = make_float2(acc[mt][nt][2], acc[mt][nt][3]);
            *(float2*)(O + ((size_t)b * H_DIM + r) * R_DIM + c)     = v0;
            *(float2*)(O + ((size_t)b * H_DIM + r + 8) * R_DIM + c) = v1;
        }
    }
}

// ---------------------------------------------------------------------------
extern "C" void kernel_launch(void* const* d_in, const int* in_sizes, int n_in,
                              void* d_out, int out_size) {
    (void)in_sizes; (void)n_in; (void)out_size;
    const float* N     = (const float*)d_in[0];
    const float* A     = (const float*)d_in[1];
    const float* alpha = (const float*)d_in[2];
    const float* gamma = (const float*)d_in[3];
    float* out = (float*)d_out;

    cudaFuncSetAttribute(k4_gemm, cudaFuncAttributeMaxDynamicSharedMemorySize,
                         2 * BUF_H * (int)sizeof(__half));

    dim3 g1(KSPLIT, B_DIM);
    k1_gram<<<g1, 256>>>(N);

    k2_inv<<<B_DIM, 1024>>>(alpha, gamma);

    dim3 g3(W_DIM / 1024, R_DIM / 16, B_DIM);
    k3_pt<<<g3, 256>>>(N, gamma);

    dim3 g4(H_DIM / BM, B_DIM);
    k4_gemm<<<g4, NTHREADS, 2 * BUF_H * (int)sizeof(__half)>>>(A, out);
}

// round 7
// speedup vs baseline: 1.5958x; 1.5958x over previous
#include <cuda_runtime.h>
#include <cuda_fp16.h>
#include <cstdint>

#define B_DIM 8
#define R_DIM 128
#define H_DIM 4096
#define W_DIM 4096
#define KSPLIT 16

// Scratch (device globals: allocation-free per harness rules)
__device__ float  g_part[KSPLIT * B_DIM * R_DIM * R_DIM]; // 8 MB partial Gram
__device__ float  g_Q[B_DIM * R_DIM * R_DIM];             // 512KB Q = 2g*C^-1
__device__ __half g_Nh[B_DIM * R_DIM * W_DIM];            // 8 MB N hi (fp16)
__device__ __half g_Nl[B_DIM * R_DIM * W_DIM];            // 8 MB N lo (fp16)
__device__ float  g_AN[B_DIM * H_DIM * R_DIM];            // 16 MB AN = A @ N^T

// ---------------------------------------------------------------------------
// K0: split N (fp32) into fp16 hi/lo pair, elementwise.
// ---------------------------------------------------------------------------
__global__ void __launch_bounds__(256) k0_split(const float* __restrict__ Nn) {
    size_t e = ((size_t)blockIdx.x * 256 + threadIdx.x) * 4;
    float4 v = *(const float4*)(Nn + e);
    __half h0 = __float2half_rn(v.x), h1 = __float2half_rn(v.y);
    __half h2 = __float2half_rn(v.z), h3 = __float2half_rn(v.w);
    __half l0 = __float2half_rn(v.x - __half2float(h0));
    __half l1 = __float2half_rn(v.y - __half2float(h1));
    __half l2 = __float2half_rn(v.z - __half2float(h2));
    __half l3 = __float2half_rn(v.w - __half2float(h3));
    __half2 hh0 = __halves2half2(h0, h1), hh1 = __halves2half2(h2, h3);
    __half2 ll0 = __halves2half2(l0, l1), ll1 = __halves2half2(l2, l3);
    *(uint2*)(g_Nh + e) = make_uint2(*(uint32_t*)&hh0, *(uint32_t*)&hh1);
    *(uint2*)(g_Nl + e) = make_uint2(*(uint32_t*)&ll0, *(uint32_t*)&ll1);
}

// ---------------------------------------------------------------------------
// K1: partial Gram  part[ks][b][r][s] = sum_{w in split} N[r][w]*N[s][w]
// ---------------------------------------------------------------------------
__global__ void __launch_bounds__(256) k1_gram(const float* __restrict__ N) {
    __shared__ float Ns[32][132];
    int ks = blockIdx.x, b = blockIdx.y;
    int tid = threadIdx.x;
    int tx = tid & 15, ty = tid >> 4;
    const float* Nb = N + (size_t)b * R_DIM * W_DIM;

    float acc[8][8];
#pragma unroll
    for (int i = 0; i < 8; i++)
#pragma unroll
        for (int j = 0; j < 8; j++) acc[i][j] = 0.f;

    int k0 = ks * (W_DIM / KSPLIT);
    for (int kk = k0; kk < k0 + W_DIM / KSPLIT; kk += 32) {
#pragma unroll
        for (int i = 0; i < 4; i++) {
            int u = tid + i * 256;
            int row = u >> 3, j = u & 7;
            float4 v = *(const float4*)(Nb + (size_t)row * W_DIM + kk + j * 4);
            Ns[j * 4 + 0][row] = v.x;
            Ns[j * 4 + 1][row] = v.y;
            Ns[j * 4 + 2][row] = v.z;
            Ns[j * 4 + 3][row] = v.w;
        }
        __syncthreads();
#pragma unroll
        for (int k = 0; k < 32; k++) {
            float4 a0 = *(const float4*)&Ns[k][ty * 8];
            float4 a1 = *(const float4*)&Ns[k][ty * 8 + 4];
            float4 b0 = *(const float4*)&Ns[k][tx * 8];
            float4 b1 = *(const float4*)&Ns[k][tx * 8 + 4];
            float av[8] = {a0.x, a0.y, a0.z, a0.w, a1.x, a1.y, a1.z, a1.w};
            float bv[8] = {b0.x, b0.y, b0.z, b0.w, b1.x, b1.y, b1.z, b1.w};
#pragma unroll
            for (int i = 0; i < 8; i++)
#pragma unroll
                for (int j = 0; j < 8; j++)
                    acc[i][j] = fmaf(av[i], bv[j], acc[i][j]);
        }
        __syncthreads();
    }
    float* P = g_part + (size_t)(ks * B_DIM + b) * 16384;
#pragma unroll
    for (int i = 0; i < 8; i++)
#pragma unroll
        for (int j = 0; j < 8; j += 4)
            *(float4*)&P[(ty * 8 + i) * 128 + tx * 8 + j] =
                make_float4(acc[i][j], acc[i][j + 1], acc[i][j + 2], acc[i][j + 3]);
}

// ---------------------------------------------------------------------------
// K2: C = alpha*I + 2*gamma*G; register-resident Gauss-Jordan inverse.
// Writes Q = 2*gamma * C^-1 (scale folded).
// ---------------------------------------------------------------------------
__global__ void __launch_bounds__(1024, 1) k2_inv(const float* __restrict__ alpha,
                                                  const float* __restrict__ gamma) {
    __shared__ float s_rowk[2][128];
    __shared__ float s_colk[2][128];
    __shared__ float s_invp[2];

    int b = blockIdx.x;
    int t = threadIdx.x;
    int i  = t >> 3;
    int jc = (t & 7) << 4;
    float a  = alpha[b];
    float g2 = 2.0f * gamma[b];

    float M[16];
#pragma unroll
    for (int q = 0; q < 16; q++) {
        int e = i * 128 + jc + q;
        float s = 0.f;
#pragma unroll
        for (int p = 0; p < KSPLIT; p++)
            s += g_part[((size_t)(p * B_DIM + b)) * 16384 + e];
        M[q] = g2 * s + ((jc + q) == i ? a : 0.f);
    }
    if (i == 0) {
#pragma unroll
        for (int q = 0; q < 16; q++) s_rowk[0][jc + q] = M[q];
        if (jc == 0) s_invp[0] = 1.0f / M[0];
    }
    if (jc == 0) s_colk[0][i] = M[0];
    __syncthreads();

    for (int k = 0; k < 128; k++) {
        int par = k & 1;
        float ip = s_invp[par];
        if (i == k) {
#pragma unroll
            for (int q = 0; q < 16; q++) M[q] *= ip;
            if (k >= jc && k < jc + 16) M[k - jc] = ip;
        } else {
            float c = s_colk[par][i] * ip;
#pragma unroll
            for (int q = 0; q < 16; q++)
                M[q] = fmaf(-c, s_rowk[par][jc + q], M[q]);
            if (k >= jc && k < jc + 16) M[k - jc] = -c;
        }
        int kn = k + 1;
        if (kn < 128) {
            int pn = kn & 1;
            if (i == kn) {
#pragma unroll
                for (int q = 0; q < 16; q++) s_rowk[pn][jc + q] = M[q];
                if (kn >= jc && kn < jc + 16) s_invp[pn] = 1.0f / M[kn - jc];
            }
            if (kn >= jc && kn < jc + 16) s_colk[pn][i] = M[kn - jc];
        }
        __syncthreads();
    }

    float* Qo = g_Q + (size_t)b * 16384;
#pragma unroll
    for (int q = 0; q < 16; q++)
        Qo[i * 128 + jc + q] = g2 * M[q];
}

// ---------------------------------------------------------------------------
// K4: AN[b][h][r] = sum_w A[b][h][w] * N[b][r][w]
// fp16 2-way split, 3x m16n8k16 HMMA fp32 accum (identical engine to R6 k4).
// A: LDG->split->STS register pipeline. B: cp.async of pre-split N hi/lo.
// ---------------------------------------------------------------------------
#define BM 256
#define BN 128
#define BK 32
#define NTHREADS 512
#define RS 40
#define AH_OFF 0
#define AL_OFF (256 * RS)
#define BH_OFF (512 * RS)
#define BL_OFF (640 * RS)
#define BUF_H  (768 * RS)

__device__ __forceinline__ uint32_t smem_u32(const void* p) {
    return (uint32_t)__cvta_generic_to_shared(p);
}
__device__ __forceinline__ void cp_async16(uint32_t saddr, const void* g) {
    asm volatile("cp.async.cg.shared.global [%0], [%1], 16;" :: "r"(saddr), "l"(g) : "memory");
}
__device__ __forceinline__ void ldsm_x4(uint32_t addr, uint32_t& r0, uint32_t& r1,
                                        uint32_t& r2, uint32_t& r3) {
    asm volatile("ldmatrix.sync.aligned.m8n8.x4.shared.b16 {%0,%1,%2,%3}, [%4];"
                 : "=r"(r0), "=r"(r1), "=r"(r2), "=r"(r3) : "r"(addr));
}
__device__ __forceinline__ void mma_f16(float* d, const uint32_t* a, const uint32_t* b) {
    asm volatile(
        "mma.sync.aligned.m16n8k16.row.col.f32.f16.f16.f32 "
        "{%0,%1,%2,%3}, {%4,%5,%6,%7}, {%8,%9}, {%0,%1,%2,%3};"
        : "+f"(d[0]), "+f"(d[1]), "+f"(d[2]), "+f"(d[3])
        : "r"(a[0]), "r"(a[1]), "r"(a[2]), "r"(a[3]),
          "r"(b[0]), "r"(b[1]));
}
__device__ __forceinline__ void split_h(float f, __half& h, __half& l) {
    h = __float2half_rn(f);
    l = __float2half_rn(f - __half2float(h));
}

__global__ void __launch_bounds__(NTHREADS, 1) k4_an(const float* __restrict__ A) {
    extern __shared__ __half smh[];
    int b  = blockIdx.y;
    int m0 = blockIdx.x * BM;
    int tid = threadIdx.x;
    int lane = tid & 31, wid = tid >> 5;
    int wm = wid & 3;
    int wn = wid >> 2;

    const float*  Ab  = A + (size_t)b * H_DIM * W_DIM;
    const __half* Bhg = g_Nh + (size_t)b * R_DIM * W_DIM;
    const __half* Blg = g_Nl + (size_t)b * R_DIM * W_DIM;

    float acc[4][4][4];
#pragma unroll
    for (int mt = 0; mt < 4; mt++)
#pragma unroll
        for (int nt = 0; nt < 4; nt++)
#pragma unroll
            for (int r = 0; r < 4; r++) acc[mt][nt][r] = 0.f;

    float4 a4[4];
    int brow = tid >> 2, bcol = tid & 3;

    auto ldg_A = [&](int kk) {
#pragma unroll
        for (int i = 0; i < 4; i++) {
            int v = tid + i * NTHREADS;
            int row = v >> 3, kc = v & 7;
            a4[i] = *(const float4*)(Ab + (size_t)(m0 + row) * W_DIM + kk + kc * 4);
        }
    };
    auto cpb = [&](int bufsel, int kk) {
        __half* base = smh + bufsel * BUF_H;
        cp_async16(smem_u32(base + BH_OFF + brow * RS + bcol * 8),
                   Bhg + (size_t)brow * W_DIM + kk + bcol * 8);
        cp_async16(smem_u32(base + BL_OFF + brow * RS + bcol * 8),
                   Blg + (size_t)brow * W_DIM + kk + bcol * 8);
        asm volatile("cp.async.commit_group;" ::: "memory");
    };
    auto sts_A = [&](int bufsel) {
        __half* base = smh + bufsel * BUF_H;
#pragma unroll
        for (int i = 0; i < 4; i++) {
            int v = tid + i * NTHREADS;
            int row = v >> 3, kc = v & 7;
            __half hx, lx, hy, ly, hz, lz, hw, lw;
            split_h(a4[i].x, hx, lx);
            split_h(a4[i].y, hy, ly);
            split_h(a4[i].z, hz, lz);
            split_h(a4[i].w, hw, lw);
            __half2* ph = (__half2*)(base + AH_OFF + row * RS + kc * 4);
            ph[0] = __halves2half2(hx, hy);
            ph[1] = __halves2half2(hz, hw);
            __half2* pl = (__half2*)(base + AL_OFF + row * RS + kc * 4);
            pl[0] = __halves2half2(lx, ly);
            pl[1] = __halves2half2(lz, lw);
        }
    };

    ldg_A(0);
    cpb(0, 0);

    const int KITERS = W_DIM / BK;
    for (int kb = 0; kb < KITERS; kb++) {
        sts_A(kb & 1);
        asm volatile("cp.async.wait_group 0;" ::: "memory");
        __syncthreads();
        if (kb + 1 < KITERS) {
            ldg_A((kb + 1) * BK);
            cpb((kb + 1) & 1, (kb + 1) * BK);
        }

        uint32_t sbase = smem_u32(smh + (kb & 1) * BUF_H);

#pragma unroll
        for (int ks = 0; ks < 2; ks++) {
            uint32_t bhi[4][2], blo[4][2];
            int idx = lane >> 3;
            int kboff = ks * 32 + (idx & 1) * 16;
#pragma unroll
            for (int h = 0; h < 2; h++) {
                int nrow = wn * 32 + h * 16 + (idx >> 1) * 8 + (lane & 7);
                uint32_t r0, r1, r2, r3;
                ldsm_x4(sbase + (BH_OFF + nrow * RS) * 2 + kboff, r0, r1, r2, r3);
                bhi[2 * h][0] = r0; bhi[2 * h][1] = r1;
                bhi[2 * h + 1][0] = r2; bhi[2 * h + 1][1] = r3;
                ldsm_x4(sbase + (BL_OFF + nrow * RS) * 2 + kboff, r0, r1, r2, r3);
                blo[2 * h][0] = r0; blo[2 * h][1] = r1;
                blo[2 * h + 1][0] = r2; blo[2 * h + 1][1] = r3;
            }
            int karow = ks * 32 + (lane >> 4) * 16;
#pragma unroll
            for (int mt = 0; mt < 4; mt++) {
                int arow = wm * 64 + mt * 16 + (lane & 15);
                uint32_t ah[4], al[4];
                ldsm_x4(sbase + (AH_OFF + arow * RS) * 2 + karow,
                        ah[0], ah[1], ah[2], ah[3]);
                ldsm_x4(sbase + (AL_OFF + arow * RS) * 2 + karow,
                        al[0], al[1], al[2], al[3]);
#pragma unroll
                for (int nt = 0; nt < 4; nt++) {
                    mma_f16(acc[mt][nt], al, bhi[nt]);
                    mma_f16(acc[mt][nt], ah, blo[nt]);
                    mma_f16(acc[mt][nt], ah, bhi[nt]);
                }
            }
        }
    }

    float* AN = g_AN + (size_t)b * H_DIM * R_DIM;
#pragma unroll
    for (int mt = 0; mt < 4; mt++) {
#pragma unroll
        for (int nt = 0; nt < 4; nt++) {
            int r = m0 + wm * 64 + mt * 16 + (lane >> 2);
            int c = wn * 32 + nt * 8 + (lane & 3) * 2;
            float2 v0 = make_float2(acc[mt][nt][0], acc[mt][nt][1]);
            float2 v1 = make_float2(acc[mt][nt][2], acc[mt][nt][3]);
            *(float2*)(AN + (size_t)r * R_DIM + c)       = v0;
            *(float2*)(AN + (size_t)(r + 8) * R_DIM + c) = v1;
        }
    }
}

// ---------------------------------------------------------------------------
// K5: out[b][h][s] = sum_r AN[b][h][r] * Q[b][r][s]   (fp32, exact)
// Per block: 128 h x 128 s, K=128. Q fully resident in smem.
// ---------------------------------------------------------------------------
#define K5_SMEM ((128 * 132 + 16 * 132) * 4)

__global__ void __launch_bounds__(256) k5_out(float* __restrict__ O) {
    extern __shared__ float s5[];
    float* Qs  = s5;               // [128][132]
    float* ANs = s5 + 128 * 132;   // [16][132]   ANs[k][h]
    int b  = blockIdx.y;
    int h0 = blockIdx.x * 128;
    int tid = threadIdx.x;
    int tx = tid & 15, ty = tid >> 4;
    const float* Qb  = g_Q  + (size_t)b * 16384;
    const float* ANb = g_AN + ((size_t)b * H_DIM + h0) * R_DIM;

    for (int e = tid; e < 128 * 32; e += 256) {
        int r = e >> 5, c4 = e & 31;
        float4 v = *(const float4*)(Qb + r * 128 + c4 * 4);
        float* dst = Qs + r * 132 + c4 * 4;
        dst[0] = v.x; dst[1] = v.y; dst[2] = v.z; dst[3] = v.w;
    }

    float acc[8][8];
#pragma unroll
    for (int i = 0; i < 8; i++)
#pragma unroll
        for (int j = 0; j < 8; j++) acc[i][j] = 0.f;

    for (int r0 = 0; r0 < 128; r0 += 16) {
        for (int e = tid; e < 512; e += 256) {   // 512 float4 units
            int h = e >> 2, q = e & 3;
            float4 v = *(const float4*)(ANb + (size_t)h * R_DIM + r0 + q * 4);
            ANs[(q * 4 + 0) * 132 + h] = v.x;
            ANs[(q * 4 + 1) * 132 + h] = v.y;
            ANs[(q * 4 + 2) * 132 + h] = v.z;
            ANs[(q * 4 + 3) * 132 + h] = v.w;
        }
        __syncthreads();
#pragma unroll
        for (int k = 0; k < 16; k++) {
            float4 a0 = *(const float4*)&ANs[k * 132 + ty * 8];
            float4 a1 = *(const float4*)&ANs[k * 132 + ty * 8 + 4];
            float4 b0 = *(const float4*)&Qs[(r0 + k) * 132 + tx * 8];
            float4 b1 = *(const float4*)&Qs[(r0 + k) * 132 + tx * 8 + 4];
            float av[8] = {a0.x, a0.y, a0.z, a0.w, a1.x, a1.y, a1.z, a1.w};
            float bv[8] = {b0.x, b0.y, b0.z, b0.w, b1.x, b1.y, b1.z, b1.w};
#pragma unroll
            for (int i = 0; i < 8; i++)
#pragma unroll
                for (int j = 0; j < 8; j++)
                    acc[i][j] = fmaf(av[i], bv[j], acc[i][j]);
        }
        __syncthreads();
    }

#pragma unroll
    for (int i = 0; i < 8; i++) {
        float* orow = O + ((size_t)b * H_DIM + h0 + ty * 8 + i) * R_DIM + tx * 8;
        *(float4*)(orow)     = make_float4(acc[i][0], acc[i][1], acc[i][2], acc[i][3]);
        *(float4*)(orow + 4) = make_float4(acc[i][4], acc[i][5], acc[i][6], acc[i][7]);
    }
}

// ---------------------------------------------------------------------------
// Fork/join stream resources, created once at load (before harness mem
// checkpoints). No device memory is allocated by this file.
// ---------------------------------------------------------------------------
namespace {
struct AuxStreams {
    cudaStream_t s2 = nullptr;
    cudaEvent_t  evA = nullptr, evB = nullptr;
    bool ok = false;
    AuxStreams() {
        ok = (cudaStreamCreateWithFlags(&s2, cudaStreamNonBlocking) == cudaSuccess) &&
             (cudaEventCreateWithFlags(&evA, cudaEventDisableTiming) == cudaSuccess) &&
             (cudaEventCreateWithFlags(&evB, cudaEventDisableTiming) == cudaSuccess);
    }
};
AuxStreams g_aux;
}

extern "C" void kernel_launch(void* const* d_in, const int* in_sizes, int n_in,
                              void* d_out, int out_size) {
    (void)in_sizes; (void)n_in; (void)out_size;
    const float* N     = (const float*)d_in[0];
    const float* A     = (const float*)d_in[1];
    const float* alpha = (const float*)d_in[2];
    const float* gamma = (const float*)d_in[3];
    float* out = (float*)d_out;

    cudaFuncSetAttribute(k4_an, cudaFuncAttributeMaxDynamicSharedMemorySize,
                         2 * BUF_H * (int)sizeof(__half));
    cudaFuncSetAttribute(k5_out, cudaFuncAttributeMaxDynamicSharedMemorySize, K5_SMEM);

    bool fork = g_aux.ok;
    dim3 g1(KSPLIT, B_DIM);

    if (fork) {
        // fork: gram + inverse run concurrently with the big GEMM
        cudaEventRecord(g_aux.evA, 0);
        cudaStreamWaitEvent(g_aux.s2, g_aux.evA, 0);
        k1_gram<<<g1, 256, 0, g_aux.s2>>>(N);
        k2_inv<<<B_DIM, 1024, 0, g_aux.s2>>>(alpha, gamma);
    } else {
        k1_gram<<<g1, 256>>>(N);
        k2_inv<<<B_DIM, 1024>>>(alpha, gamma);
    }

    // main branch: split N, then big GEMM AN = A @ N^T
    k0_split<<<(B_DIM * R_DIM * W_DIM) / 1024, 256>>>(N);
    dim3 g4(H_DIM / BM, B_DIM);
    k4_an<<<g4, NTHREADS, 2 * BUF_H * (int)sizeof(__half)>>>(A);

    if (fork) {
        // join
        cudaEventRecord(g_aux.evB, g_aux.s2);
        cudaStreamWaitEvent(0, g_aux.evB, 0);
    }

    dim3 g5(H_DIM / 128, B_DIM);
    k5_out<<<g5, 256, K5_SMEM>>>(out);
}